// round 2
// baseline (speedup 1.0000x reference)
#include <cuda_runtime.h>
#include <cstdint>
#include <math.h>

// ---------------- problem constants ----------------
#define T_STEPS   256
#define BATCH     1024
#define HIDN      256
#define EMBD      10
#define NCLS      10

// ---------------- launch geometry ------------------
#define CLUSTER   8
#define NCLUSTERS 16
#define GRID_X    (CLUSTER * NCLUSTERS)   // 128 CTAs
#define NTHREADS  256

#define MROWS     64                      // batch rows per cluster
#define NC        128                     // output cols per CTA = 32 kk * 4 gates
#define KTOT      (HIDN + EMBD)           // 266 (h rows + x-embedding rows)

// ---------------- smem layout (floats) -------------
#define WHS_F 0                           // Whs[KTOT][NC], j' = kk*4 + gate
#define HT_F  (KTOT * NC)                 // hT[KTOT][MROWS] (k-major, rows 256.. = x emb)
#define CS_F  (HT_F + KTOT * MROWS)       // c state [32][MROWS] (own k-slice)
#define BS_F  (CS_F + 32 * MROWS)         // bias [NC]
#define SMEMF (BS_F + NC)
#define SMEM_BYTES (SMEMF * 4)            // 212,992 bytes

// ---------------- helpers --------------------------
__device__ __forceinline__ uint32_t smem_u32(const void* p) {
    uint32_t a;
    asm("{ .reg .u64 t; cvta.to.shared.u64 t, %1; cvt.u32.u64 %0, t; }"
        : "=r"(a) : "l"(p));
    return a;
}
__device__ __forceinline__ uint32_t ctarank() {
    uint32_t r; asm("mov.u32 %0, %%cluster_ctarank;" : "=r"(r)); return r;
}
__device__ __forceinline__ uint32_t mapa_u32(uint32_t a, uint32_t r) {
    uint32_t d; asm("mapa.shared::cluster.u32 %0, %1, %2;" : "=r"(d) : "r"(a), "r"(r));
    return d;
}
__device__ __forceinline__ void cluster_sync_() {
    asm volatile("barrier.cluster.arrive.aligned;" ::: "memory");
    asm volatile("barrier.cluster.wait.aligned;" ::: "memory");
}

#define FMA2(d, a, b) asm("fma.rn.f32x2 %0, %1, %2, %0;" : "+l"(d) : "l"(a), "l"(b))

__global__ __launch_bounds__(NTHREADS, 1) __cluster_dims__(CLUSTER, 1, 1)
void lstm_kernel(const int*   __restrict__ x,
                 const float* __restrict__ emb,
                 const float* __restrict__ Wgx, const float* __restrict__ Wgh, const float* __restrict__ bg,
                 const float* __restrict__ Wix, const float* __restrict__ Wih, const float* __restrict__ bi,
                 const float* __restrict__ Wfx, const float* __restrict__ Wfh, const float* __restrict__ bf,
                 const float* __restrict__ Wox, const float* __restrict__ Woh, const float* __restrict__ bo,
                 const float* __restrict__ Wph, const float* __restrict__ bp,
                 float* __restrict__ out)
{
    extern __shared__ float smf[];
    const int      tid      = threadIdx.x;
    const uint32_t rank     = ctarank();                 // 0..7 within cluster
    const int      rowBase  = (blockIdx.x >> 3) * MROWS; // cluster id * 64
    const uint32_t smemBase = smem_u32(smf);

    // ---- Stage weights into SMEM: Whs[k][kk*4+g], k-rows 256..265 hold Wx ----
    {
        const float* Wh4[4] = {Wgh, Wih, Wfh, Woh};
        const float* Wx4[4] = {Wgx, Wix, Wfx, Wox};
        const float* b4[4]  = {bg, bi, bf, bo};
        #pragma unroll
        for (int g = 0; g < 4; ++g) {
            for (int idx = tid; idx < HIDN * 32; idx += NTHREADS) {
                int k = idx >> 5, kk = idx & 31;
                smf[WHS_F + k * NC + kk * 4 + g] = Wh4[g][k * HIDN + rank * 32 + kk];
            }
            for (int idx = tid; idx < EMBD * 32; idx += NTHREADS) {
                int e = idx >> 5, kk = idx & 31;
                smf[WHS_F + (HIDN + e) * NC + kk * 4 + g] = Wx4[g][e * HIDN + rank * 32 + kk];
            }
            if (tid < 32) smf[BS_F + tid * 4 + g] = b4[g][rank * 32 + tid];
        }
    }
    // zero h (incl. emb rows) and c
    for (int idx = tid; idx < KTOT * MROWS; idx += NTHREADS) smf[HT_F + idx] = 0.0f;
    for (int idx = tid; idx < 32 * MROWS;  idx += NTHREADS) smf[CS_F + idx] = 0.0f;
    __syncthreads();

    // GEMM thread tiling: 4 rows (m) x 8 cols (j') per thread.
    // tm selects m-group (warp-contiguous -> a-loads conflict-light),
    // tj selects j'-group (warp-broadcast b-loads).
    const int tm = tid & 15;   // m base = tm*4
    const int tj = tid >> 4;   // kk in {2tj, 2tj+1}, all 4 gates

    const uint32_t waB = smemBase + (WHS_F) * 4 + tj * 32;  // 8 floats of Whs row
    const uint32_t haB = smemBase + (HT_F) * 4 + tm * 16;   // 4 floats of hT row
    const uint32_t bsA = smemBase + (BS_F) * 4 + tj * 32;

    unsigned long long bb0, bb1, bb2, bb3;
    asm("ld.shared.v2.b64 {%0,%1},[%2];" : "=l"(bb0), "=l"(bb1) : "r"(bsA));
    asm("ld.shared.v2.b64 {%0,%1},[%2];" : "=l"(bb2), "=l"(bb3) : "r"(bsA + 16));

    for (int t = 0; t < T_STEPS; ++t) {
        // ---- gather x-embedding for this step into hT rows 256..265 ----
        if (tid < MROWS) {
            int tok = __ldg(&x[(rowBase + tid) * T_STEPS + t]);
            const float* er = emb + tok * EMBD;
            #pragma unroll
            for (int e = 0; e < EMBD; ++e)
                smf[HT_F + (HIDN + e) * MROWS + tid] = __ldg(&er[e]);
        }
        __syncthreads();

        // ---- z = bias + [h | x_emb] @ [Wh | Wx]  (packed f32x2 FMAs) ----
        unsigned long long acc[16];
        #pragma unroll
        for (int mi = 0; mi < 4; ++mi) {
            acc[mi * 4 + 0] = bb0; acc[mi * 4 + 1] = bb1;
            acc[mi * 4 + 2] = bb2; acc[mi * 4 + 3] = bb3;
        }

        #pragma unroll 2
        for (int k = 0; k < KTOT; ++k) {
            unsigned long long b0, b1, b2, b3;
            uint32_t wa = waB + (uint32_t)k * (NC * 4);
            asm("ld.shared.v2.b64 {%0,%1},[%2];" : "=l"(b0), "=l"(b1) : "r"(wa));
            asm("ld.shared.v2.b64 {%0,%1},[%2];" : "=l"(b2), "=l"(b3) : "r"(wa + 16));
            float a0, a1, a2, a3;
            asm("ld.shared.v4.f32 {%0,%1,%2,%3},[%4];"
                : "=f"(a0), "=f"(a1), "=f"(a2), "=f"(a3)
                : "r"(haB + (uint32_t)k * (MROWS * 4)));
            unsigned long long p0, p1, p2, p3;
            asm("mov.b64 %0,{%1,%1};" : "=l"(p0) : "f"(a0));
            asm("mov.b64 %0,{%1,%1};" : "=l"(p1) : "f"(a1));
            asm("mov.b64 %0,{%1,%1};" : "=l"(p2) : "f"(a2));
            asm("mov.b64 %0,{%1,%1};" : "=l"(p3) : "f"(a3));
            FMA2(acc[0],  p0, b0); FMA2(acc[1],  p0, b1); FMA2(acc[2],  p0, b2); FMA2(acc[3],  p0, b3);
            FMA2(acc[4],  p1, b0); FMA2(acc[5],  p1, b1); FMA2(acc[6],  p1, b2); FMA2(acc[7],  p1, b3);
            FMA2(acc[8],  p2, b0); FMA2(acc[9],  p2, b1); FMA2(acc[10], p2, b2); FMA2(acc[11], p2, b3);
            FMA2(acc[12], p3, b0); FMA2(acc[13], p3, b1); FMA2(acc[14], p3, b2); FMA2(acc[15], p3, b3);
        }

        // ---- gates + state update (all 4 gates are register-local per (m,kk)) ----
        float h0[4], h1[4];
        #pragma unroll
        for (int mi = 0; mi < 4; ++mi) {
            #pragma unroll
            for (int kkl = 0; kkl < 2; ++kkl) {
                float zg, zi2, zf, zo;
                asm("mov.b64 {%0,%1},%2;" : "=f"(zg), "=f"(zi2) : "l"(acc[mi * 4 + kkl * 2 + 0]));
                asm("mov.b64 {%0,%1},%2;" : "=f"(zf), "=f"(zo)  : "l"(acc[mi * 4 + kkl * 2 + 1]));
                float gg = tanhf(zg);
                float ii = 1.0f / (1.0f + expf(-zi2));
                float ff = 1.0f / (1.0f + expf(-zf));
                float oo = 1.0f / (1.0f + expf(-zo));
                int kk = 2 * tj + kkl;
                int m  = tm * 4 + mi;
                float cold = smf[CS_F + kk * MROWS + m];
                float cn = gg * ii + cold * ff;
                smf[CS_F + kk * MROWS + m] = cn;
                float hn = tanhf(cn) * oo;
                if (kkl == 0) h0[mi] = hn; else h1[mi] = hn;
            }
        }

        // all CTAs must be done READING hT before anyone overwrites it
        cluster_sync_();

        // ---- broadcast our 32 h-columns to all 8 cluster SMEM replicas ----
        {
            uint32_t own = smemBase +
                (uint32_t)(HT_F + (rank * 32 + 2 * tj) * MROWS + tm * 4) * 4;
            #pragma unroll
            for (int p = 0; p < CLUSTER; ++p) {
                uint32_t pa = mapa_u32(own, (uint32_t)p);
                asm volatile("st.shared::cluster.v4.f32 [%0],{%1,%2,%3,%4};"
                             :: "r"(pa), "f"(h0[0]), "f"(h0[1]), "f"(h0[2]), "f"(h0[3]) : "memory");
                asm volatile("st.shared::cluster.v4.f32 [%0],{%1,%2,%3,%4};"
                             :: "r"(pa + MROWS * 4), "f"(h1[0]), "f"(h1[1]), "f"(h1[2]), "f"(h1[3]) : "memory");
            }
        }

        // h(t) fully exchanged & visible
        cluster_sync_();
    }

    // ---- final projection: out = h_T @ Wph + bp  (each CTA: 8 rows x 10 cls) ----
    if (tid < 8 * NCLS) {
        int mi = tid / NCLS, cl = tid - mi * NCLS;
        int m  = (int)rank * 8 + mi;
        float s = __ldg(&bp[cl]);
        #pragma unroll 4
        for (int k = 0; k < HIDN; ++k)
            s += smf[HT_F + k * MROWS + m] * __ldg(&Wph[k * NCLS + cl]);
        out[(rowBase + m) * NCLS + cl] = s;
    }
}

// ---------------- host launch ----------------------
extern "C" void kernel_launch(void* const* d_in, const int* in_sizes, int n_in,
                              void* d_out, int out_size)
{
    const int*   x   = (const int*)  d_in[0];
    const float* emb = (const float*)d_in[1];
    const float* Wgx = (const float*)d_in[2];
    const float* Wgh = (const float*)d_in[3];
    const float* bg  = (const float*)d_in[4];
    const float* Wix = (const float*)d_in[5];
    const float* Wih = (const float*)d_in[6];
    const float* bi  = (const float*)d_in[7];
    const float* Wfx = (const float*)d_in[8];
    const float* Wfh = (const float*)d_in[9];
    const float* bf  = (const float*)d_in[10];
    const float* Wox = (const float*)d_in[11];
    const float* Woh = (const float*)d_in[12];
    const float* bo  = (const float*)d_in[13];
    const float* Wph = (const float*)d_in[14];
    const float* bp  = (const float*)d_in[15];

    cudaFuncSetAttribute(lstm_kernel,
                         cudaFuncAttributeMaxDynamicSharedMemorySize, SMEM_BYTES);

    lstm_kernel<<<GRID_X, NTHREADS, SMEM_BYTES>>>(
        x, emb, Wgx, Wgh, bg, Wix, Wih, bi, Wfx, Wfh, bf, Wox, Woh, bo,
        Wph, bp, (float*)d_out);
}